// round 7
// baseline (speedup 1.0000x reference)
#include <cuda_runtime.h>
#include <cuda_bf16.h>
#include <cstdint>

#define NN 20000
#define EE 320000
#define DD 128
#define LL 5
#define EVV 5
#define BN_EPS 1e-5f

// ---------------- device scratch (no allocation allowed) ----------------
__device__ float g_h1[NN * DD];
__device__ float g_h2[NN * DD];
__device__ float g_Y1[NN * DD];
__device__ float g_Y2[NN * DD];
__device__ __nv_bfloat16 g_Whi[2 * LL * DD * DD];
__device__ __nv_bfloat16 g_Wlo[2 * LL * DD * DD];
__device__ int   g_deg[NN];
__device__ int   g_off[NN + 1];
__device__ int   g_cur[NN];
__device__ int   g_pack[EE];     // (src << 3) | attr
__device__ float g_sumL[LL * 2 * DD];
__device__ float g_sqL[LL * 2 * DD];

// ---------------- PTX helpers ----------------
__device__ __forceinline__ uint32_t smem_u32(const void* p) {
    uint32_t a;
    asm("{ .reg .u64 t; cvta.to.shared.u64 t, %1; cvt.u32.u64 %0, t; }" : "=r"(a) : "l"(p));
    return a;
}
__device__ __forceinline__ void ldsm4(uint32_t* r, uint32_t addr) {
    asm volatile("ldmatrix.sync.aligned.m8n8.x4.shared.b16 {%0,%1,%2,%3}, [%4];"
                 : "=r"(r[0]), "=r"(r[1]), "=r"(r[2]), "=r"(r[3]) : "r"(addr));
}
__device__ __forceinline__ void mma16816(float* d, const uint32_t* a, const uint32_t* b) {
    asm volatile(
        "mma.sync.aligned.m16n8k16.row.col.f32.bf16.bf16.f32 "
        "{%0,%1,%2,%3}, {%4,%5,%6,%7}, {%8,%9}, {%0,%1,%2,%3};"
        : "+f"(d[0]), "+f"(d[1]), "+f"(d[2]), "+f"(d[3])
        : "r"(a[0]), "r"(a[1]), "r"(a[2]), "r"(a[3]), "r"(b[0]), "r"(b[1]));
}
__device__ __forceinline__ void cp16(uint32_t dst, const void* src) {
    asm volatile("cp.async.cg.shared.global [%0], [%1], 16;" :: "r"(dst), "l"(src));
}
__device__ __forceinline__ void cp_commit() {
    asm volatile("cp.async.commit_group;" ::: "memory");
}
__device__ __forceinline__ void cp_wait0() {
    asm volatile("cp.async.wait_group 0;" ::: "memory");
}

// ---------------- CSR build ----------------
__global__ void k_zero_deg() {
    int i = blockIdx.x * blockDim.x + threadIdx.x;
    if (i < NN) g_deg[i] = 0;
}

__global__ void k_hist(const int* __restrict__ ei) {
    int e = blockIdx.x * blockDim.x + threadIdx.x;
    if (e < EE) atomicAdd(&g_deg[ei[EE + e]], 1);
}

__global__ void k_scan() {
    __shared__ int wsum[32];
    __shared__ int carry;
    int tid = threadIdx.x, lane = tid & 31, w = tid >> 5;
    if (tid == 0) { carry = 0; g_off[0] = 0; }
    __syncthreads();
    for (int base = 0; base < NN; base += 1024) {
        int i = base + tid;
        int v = (i < NN) ? g_deg[i] : 0;
        int x = v;
#pragma unroll
        for (int o = 1; o < 32; o <<= 1) {
            int y = __shfl_up_sync(0xffffffffu, x, o);
            if (lane >= o) x += y;
        }
        if (lane == 31) wsum[w] = x;
        __syncthreads();
        if (w == 0) {
            int s = wsum[lane];
#pragma unroll
            for (int o = 1; o < 32; o <<= 1) {
                int y = __shfl_up_sync(0xffffffffu, s, o);
                if (lane >= o) s += y;
            }
            wsum[lane] = s;
        }
        __syncthreads();
        int incl = x + (w ? wsum[w - 1] : 0) + carry;
        if (i < NN) { g_off[i + 1] = incl; g_cur[i] = incl - v; }
        __syncthreads();
        if (tid == 1023) carry = incl;
        __syncthreads();
    }
}

__global__ void k_scatter(const int* __restrict__ ei, const int* __restrict__ ea) {
    int e = blockIdx.x * blockDim.x + threadIdx.x;
    if (e < EE) {
        int d = ei[EE + e];
        int p = atomicAdd(&g_cur[d], 1);
        g_pack[p] = (ei[e] << 3) | ea[e];
    }
}

// ---------------- weight pre-conversion + stat zeroing ----------------
__global__ void k_convW(const float* __restrict__ Wfull) {
    int i = blockIdx.x * blockDim.x + threadIdx.x;
    if (i < LL * 2 * DD) { g_sumL[i] = 0.f; g_sqL[i] = 0.f; }
    if (i >= 2 * LL * DD * DD) return;
    float v = Wfull[i];
    __nv_bfloat16 h = __float2bfloat16(v);
    g_Whi[i] = h;
    g_Wlo[i] = __float2bfloat16(v - __bfloat162float(h));
}

// ---------------- node encoding ----------------
__global__ void k_encode(const int* __restrict__ x,
                         const float* __restrict__ ne1,
                         const float* __restrict__ ne2) {
    int idx = blockIdx.x * blockDim.x + threadIdx.x;
    if (idx >= NN * 32) return;
    int n = idx >> 5, c = idx & 31;
    int xv = x[n];
    ((float4*)g_h1)[n * 32 + c] = ((const float4*)ne1)[xv * 32 + c];
    ((float4*)g_h2)[n * 32 + c] = ((const float4*)ne2)[xv * 32 + c];
}

// ---------------- fused aggregate + HMMA GEMM ---------------------------
// Per block: 64 nodes of one tower. Gather-aggregate into swizzled bf16 hi/lo
// SMEM tiles, cp.async W hi/lo concurrently, then Y = A @ W^T + b with fused
// BN stat accumulation.
// SMEM: Ahi 16KB | Alo 16KB | Whi 32KB | Wlo 32KB | edge table 2.5KB
#define SM_AHI  0
#define SM_ALO  16384
#define SM_WHI  32768
#define SM_WLO  65536
#define SM_ET   98304
#define SM_TOTAL (98304 + 2560)

__device__ __forceinline__ void split4(float4 r, uint2* hi, uint2* lo) {
    __nv_bfloat16 hx = __float2bfloat16(r.x), hy = __float2bfloat16(r.y);
    __nv_bfloat16 hz = __float2bfloat16(r.z), hw = __float2bfloat16(r.w);
    __nv_bfloat16 lx = __float2bfloat16(r.x - __bfloat162float(hx));
    __nv_bfloat16 ly = __float2bfloat16(r.y - __bfloat162float(hy));
    __nv_bfloat16 lz = __float2bfloat16(r.z - __bfloat162float(hz));
    __nv_bfloat16 lw = __float2bfloat16(r.w - __bfloat162float(hw));
    hi->x = (uint32_t)__bfloat16_as_ushort(hx) | ((uint32_t)__bfloat16_as_ushort(hy) << 16);
    hi->y = (uint32_t)__bfloat16_as_ushort(hz) | ((uint32_t)__bfloat16_as_ushort(hw) << 16);
    lo->x = (uint32_t)__bfloat16_as_ushort(lx) | ((uint32_t)__bfloat16_as_ushort(ly) << 16);
    lo->y = (uint32_t)__bfloat16_as_ushort(lz) | ((uint32_t)__bfloat16_as_ushort(lw) << 16);
}

__global__ __launch_bounds__(256, 2) void k_gin_fused(const float* __restrict__ eemb,
                                                      const float* __restrict__ eps_ptr,
                                                      const float* __restrict__ bfull,
                                                      int layer) {
    extern __shared__ char smem[];
    uint32_t sbase = smem_u32(smem);
    int tid = threadIdx.x;
    int wid = tid >> 5, lane = tid & 31;

    int t = blockIdx.y;
    const __nv_bfloat16* Whi = g_Whi + (t * LL + layer) * DD * DD;
    const __nv_bfloat16* Wlo = g_Wlo + (t * LL + layer) * DD * DD;
    const float* et = eemb + (t * LL + layer) * EVV * DD;
    float* Y = t ? g_Y2 : g_Y1;
    const float4* hv = (const float4*)(t ? g_h2 : g_h1);
    const float* bp = bfull + (t * LL + layer) * DD;
    int m0 = blockIdx.x * 64;

    // Issue W cp.async first (overlaps with gather phase)
    for (int i = tid; i < 4096; i += 256) {
        int half = i >> 11;                 // 0 = hi, 1 = lo
        int idx = i & 2047;
        int row = idx >> 4, ch = idx & 15;
        uint32_t so = (uint32_t)row * 256u + (uint32_t)((ch ^ (row & 7)) << 4);
        const char* src = (const char*)((half ? Wlo : Whi) + (size_t)row * DD) + ch * 16;
        cp16(sbase + (half ? SM_WLO : SM_WHI) + so, src);
    }
    cp_commit();

    // Edge table to smem
    float4* s_et = (float4*)(smem + SM_ET);
    for (int i = tid; i < EVV * 32; i += 256)
        s_et[i] = ((const float4*)et)[i];
    __syncthreads();

    float e1 = 1.f + eps_ptr[t * LL + layer];

    // Gather-aggregate: warp w handles rows w*8 .. w*8+7
#pragma unroll 1
    for (int i = 0; i < 8; i++) {
        int row = wid * 8 + i;
        int n = m0 + row;
        float4 r = make_float4(0.f, 0.f, 0.f, 0.f);
        if (n < NN) {
            int beg = g_off[n], deg = g_off[n + 1] - beg;
            for (int base = 0; base < deg; base += 32) {
                int idx = base + lane;
                int pk = (idx < deg) ? __ldg(&g_pack[beg + idx]) : 0;
                int cnt = min(32, deg - base);
                for (int k = 0; k < cnt; k++) {
                    int p = __shfl_sync(0xffffffffu, pk, k);
                    float4 v = hv[(p >> 3) * 32 + lane];
                    float4 tt = s_et[(p & 7) * 32 + lane];
                    r.x += fmaxf(v.x + tt.x, 0.f);
                    r.y += fmaxf(v.y + tt.y, 0.f);
                    r.z += fmaxf(v.z + tt.z, 0.f);
                    r.w += fmaxf(v.w + tt.w, 0.f);
                }
            }
            float4 o = hv[n * 32 + lane];
            r.x += e1 * o.x; r.y += e1 * o.y; r.z += e1 * o.z; r.w += e1 * o.w;
        }
        uint2 hi, lo;
        split4(r, &hi, &lo);
        uint32_t so = (uint32_t)row * 256u
                    + (uint32_t)((((lane >> 1)) ^ (row & 7)) << 4) + (uint32_t)(lane & 1) * 8u;
        *(uint2*)(smem + SM_AHI + so) = hi;
        *(uint2*)(smem + SM_ALO + so) = lo;
    }
    cp_wait0();
    __syncthreads();

    // MMA: warp tiling 2 (m) x 4 (n); warp tile 32x32
    int wm = wid & 1, wn = wid >> 1;
    int grp = lane >> 3, r8 = lane & 7;
    int a_row0 = wm * 32 + (grp & 1) * 8 + r8;
    int b_row0 = wn * 32 + (grp >> 1) * 8 + r8;
    int kselA = grp >> 1;
    int kselB = grp & 1;

    float acc[2][4][4];
#pragma unroll
    for (int i = 0; i < 2; i++)
#pragma unroll
        for (int j = 0; j < 4; j++)
#pragma unroll
            for (int q = 0; q < 4; q++) acc[i][j][q] = 0.f;

#pragma unroll
    for (int p = 0; p < 3; p++) {
        uint32_t Ab = sbase + ((p == 2) ? SM_ALO : SM_AHI);
        uint32_t Bb = sbase + ((p == 1) ? SM_WLO : SM_WHI);
#pragma unroll
        for (int ks = 0; ks < 8; ks++) {
            uint32_t af[2][4], bf[2][4];
            uint32_t aoff = (uint32_t)(((ks * 2 + kselA) ^ r8) << 4);
            ldsm4(af[0], Ab + (uint32_t)a_row0 * 256u + aoff);
            ldsm4(af[1], Ab + (uint32_t)(a_row0 + 16) * 256u + aoff);
            uint32_t boff = (uint32_t)(((ks * 2 + kselB) ^ r8) << 4);
            ldsm4(bf[0], Bb + (uint32_t)b_row0 * 256u + boff);
            ldsm4(bf[1], Bb + (uint32_t)(b_row0 + 16) * 256u + boff);
#pragma unroll
            for (int i = 0; i < 2; i++)
#pragma unroll
                for (int j = 0; j < 4; j++)
                    mma16816(acc[i][j], af[i], &bf[j >> 1][(j & 1) * 2]);
        }
    }

    // Epilogue: bias add, store Y, fused BN partial sums
    float* gsum = g_sumL + layer * 2 * DD + t * DD;
    float* gsq = g_sqL + layer * 2 * DD + t * DD;
    int qr = lane >> 2, qc = lane & 3;
#pragma unroll
    for (int j = 0; j < 4; j++) {
        int c0 = wn * 32 + j * 8 + qc * 2;
        float bb0 = bp[c0], bb1 = bp[c0 + 1];
        float s0 = 0.f, s1 = 0.f, q0 = 0.f, q1 = 0.f;
#pragma unroll
        for (int i = 0; i < 2; i++) {
#pragma unroll
            for (int h = 0; h < 2; h++) {
                int m = m0 + wm * 32 + i * 16 + qr + h * 8;
                float v0 = acc[i][j][h * 2 + 0] + bb0;
                float v1 = acc[i][j][h * 2 + 1] + bb1;
                if (m < NN) {
                    *(float2*)&Y[m * DD + c0] = make_float2(v0, v1);
                    s0 += v0; s1 += v1;
                    q0 += v0 * v0; q1 += v1 * v1;
                }
            }
        }
#pragma unroll
        for (int off = 4; off < 32; off <<= 1) {
            s0 += __shfl_xor_sync(0xffffffffu, s0, off);
            s1 += __shfl_xor_sync(0xffffffffu, s1, off);
            q0 += __shfl_xor_sync(0xffffffffu, q0, off);
            q1 += __shfl_xor_sync(0xffffffffu, q1, off);
        }
        if (qr == 0) {
            atomicAdd(&gsum[c0], s0);
            atomicAdd(&gsum[c0 + 1], s1);
            atomicAdd(&gsq[c0], q0);
            atomicAdd(&gsq[c0 + 1], q1);
        }
    }
}

// ---------------- BN + relu + cross-stitch ----------------
__global__ void k_bn_cross(const float* __restrict__ gam,
                           const float* __restrict__ bet,
                           const float* __restrict__ cu,
                           int layer, int last, float* __restrict__ out) {
    int idx = blockIdx.x * blockDim.x + threadIdx.x;
    if (idx >= NN * 32) return;
    int n = idx >> 5, c4 = idx & 31;
    int f = c4 * 4;
    const float inv = 1.f / (float)NN;
    const float* gsum = g_sumL + layer * 2 * DD;
    const float* gsq = g_sqL + layer * 2 * DD;

    float4 s1 = *(const float4*)&gsum[f];
    float4 q1 = *(const float4*)&gsq[f];
    float4 s2 = *(const float4*)&gsum[DD + f];
    float4 q2 = *(const float4*)&gsq[DD + f];

    float4 mu1 = make_float4(s1.x * inv, s1.y * inv, s1.z * inv, s1.w * inv);
    float4 mu2 = make_float4(s2.x * inv, s2.y * inv, s2.z * inv, s2.w * inv);
    float4 rs1 = make_float4(rsqrtf(q1.x * inv - mu1.x * mu1.x + BN_EPS),
                             rsqrtf(q1.y * inv - mu1.y * mu1.y + BN_EPS),
                             rsqrtf(q1.z * inv - mu1.z * mu1.z + BN_EPS),
                             rsqrtf(q1.w * inv - mu1.w * mu1.w + BN_EPS));
    float4 rs2 = make_float4(rsqrtf(q2.x * inv - mu2.x * mu2.x + BN_EPS),
                             rsqrtf(q2.y * inv - mu2.y * mu2.y + BN_EPS),
                             rsqrtf(q2.z * inv - mu2.z * mu2.z + BN_EPS),
                             rsqrtf(q2.w * inv - mu2.w * mu2.w + BN_EPS));

    float4 g1 = *(const float4*)&gam[(0 * LL + layer) * DD + f];
    float4 b1 = *(const float4*)&bet[(0 * LL + layer) * DD + f];
    float4 g2 = *(const float4*)&gam[(1 * LL + layer) * DD + f];
    float4 b2 = *(const float4*)&bet[(1 * LL + layer) * DD + f];

    float4 y1 = ((const float4*)g_Y1)[n * 32 + c4];
    float4 y2 = ((const float4*)g_Y2)[n * 32 + c4];

    y1.x = (y1.x - mu1.x) * rs1.x * g1.x + b1.x;
    y1.y = (y1.y - mu1.y) * rs1.y * g1.y + b1.y;
    y1.z = (y1.z - mu1.z) * rs1.z * g1.z + b1.z;
    y1.w = (y1.w - mu1.w) * rs1.w * g1.w + b1.w;
    y2.x = (y2.x - mu2.x) * rs2.x * g2.x + b2.x;
    y2.y = (y2.y - mu2.y) * rs2.y * g2.y + b2.y;
    y2.z = (y2.z - mu2.z) * rs2.z * g2.z + b2.z;
    y2.w = (y2.w - mu2.w) * rs2.w * g2.w + b2.w;

    if (!last) {
        y1.x = fmaxf(y1.x, 0.f); y1.y = fmaxf(y1.y, 0.f);
        y1.z = fmaxf(y1.z, 0.f); y1.w = fmaxf(y1.w, 0.f);
        y2.x = fmaxf(y2.x, 0.f); y2.y = fmaxf(y2.y, 0.f);
        y2.z = fmaxf(y2.z, 0.f); y2.w = fmaxf(y2.w, 0.f);
    }

    float c00 = cu[layer * 4 + 0], c01 = cu[layer * 4 + 1];
    float c10 = cu[layer * 4 + 2], c11 = cu[layer * 4 + 3];

    float4 n1 = make_float4(c00 * y1.x + c01 * y2.x, c00 * y1.y + c01 * y2.y,
                            c00 * y1.z + c01 * y2.z, c00 * y1.w + c01 * y2.w);
    float4 n2 = make_float4(c10 * n1.x + c11 * y2.x, c10 * n1.y + c11 * y2.y,
                            c10 * n1.z + c11 * y2.z, c10 * n1.w + c11 * y2.w);

    if (last) {
        ((float4*)out)[n * 32 + c4] = n1;
        ((float4*)out)[NN * 32 + n * 32 + c4] = n2;
    } else {
        ((float4*)g_h1)[n * 32 + c4] = n1;
        ((float4*)g_h2)[n * 32 + c4] = n2;
    }
}

// ---------------- launch ----------------
extern "C" void kernel_launch(void* const* d_in, const int* in_sizes, int n_in,
                              void* d_out, int out_size) {
    const int* x = (const int*)d_in[0];
    const int* ei = (const int*)d_in[1];
    const int* ea = (const int*)d_in[2];
    const float* ne1 = (const float*)d_in[3];
    const float* ne2 = (const float*)d_in[4];
    const float* eemb = (const float*)d_in[5];
    const float* eps = (const float*)d_in[6];
    const float* W = (const float*)d_in[7];
    const float* b = (const float*)d_in[8];
    const float* gam = (const float*)d_in[9];
    const float* bet = (const float*)d_in[10];
    const float* cu = (const float*)d_in[11];
    float* out = (float*)d_out;

    cudaFuncSetAttribute(k_gin_fused, cudaFuncAttributeMaxDynamicSharedMemorySize,
                         SM_TOTAL);

    k_zero_deg<<<(NN + 255) / 256, 256>>>();
    k_hist<<<(EE + 255) / 256, 256>>>(ei);
    k_scan<<<1, 1024>>>();
    k_scatter<<<(EE + 255) / 256, 256>>>(ei, ea);
    k_convW<<<(2 * LL * DD * DD + 255) / 256, 256>>>(W);
    k_encode<<<(NN * 32 + 255) / 256, 256>>>(x, ne1, ne2);

    for (int l = 0; l < LL; l++) {
        dim3 gg((NN + 63) / 64, 2);
        k_gin_fused<<<gg, 256, SM_TOTAL>>>(eemb, eps, b, l);
        k_bn_cross<<<(NN * 32 + 255) / 256, 256>>>(gam, bet, cu, l, (l == LL - 1) ? 1 : 0, out);
    }
}

// round 8
// speedup vs baseline: 1.2934x; 1.2934x over previous
#include <cuda_runtime.h>
#include <cuda_bf16.h>
#include <cstdint>

#define NN 20000
#define EE 320000
#define DD 128
#define LL 5
#define EVV 5
#define BN_EPS 1e-5f
#define MPAD 20096   // 157 * 128

// ---------------- device scratch (no allocation allowed) ----------------
__device__ float g_h1[NN * DD];
__device__ float g_h2[NN * DD];
__device__ float g_Y1[NN * DD];
__device__ float g_Y2[NN * DD];
__device__ __nv_bfloat16 g_A1hi[MPAD * DD];
__device__ __nv_bfloat16 g_A1lo[MPAD * DD];
__device__ __nv_bfloat16 g_A2hi[MPAD * DD];
__device__ __nv_bfloat16 g_A2lo[MPAD * DD];
__device__ __nv_bfloat16 g_Whi[2 * LL * DD * DD];
__device__ __nv_bfloat16 g_Wlo[2 * LL * DD * DD];
__device__ int   g_deg[NN];
__device__ int   g_off[NN + 1];
__device__ int   g_cur[NN];
__device__ int   g_pack[EE];     // (src << 3) | attr
__device__ float g_sumL[LL * 2 * DD];
__device__ float g_sqL[LL * 2 * DD];

// ---------------- PTX helpers ----------------
__device__ __forceinline__ uint32_t smem_u32(const void* p) {
    uint32_t a;
    asm("{ .reg .u64 t; cvta.to.shared.u64 t, %1; cvt.u32.u64 %0, t; }" : "=r"(a) : "l"(p));
    return a;
}
__device__ __forceinline__ void ldsm4(uint32_t* r, uint32_t addr) {
    asm volatile("ldmatrix.sync.aligned.m8n8.x4.shared.b16 {%0,%1,%2,%3}, [%4];"
                 : "=r"(r[0]), "=r"(r[1]), "=r"(r[2]), "=r"(r[3]) : "r"(addr));
}
__device__ __forceinline__ void mma16816(float* d, const uint32_t* a, const uint32_t* b) {
    asm volatile(
        "mma.sync.aligned.m16n8k16.row.col.f32.bf16.bf16.f32 "
        "{%0,%1,%2,%3}, {%4,%5,%6,%7}, {%8,%9}, {%0,%1,%2,%3};"
        : "+f"(d[0]), "+f"(d[1]), "+f"(d[2]), "+f"(d[3])
        : "r"(a[0]), "r"(a[1]), "r"(a[2]), "r"(a[3]), "r"(b[0]), "r"(b[1]));
}
__device__ __forceinline__ void cp16(uint32_t dst, const void* src) {
    asm volatile("cp.async.cg.shared.global [%0], [%1], 16;" :: "r"(dst), "l"(src));
}
__device__ __forceinline__ void cp_commit_wait() {
    asm volatile("cp.async.commit_group;" ::: "memory");
    asm volatile("cp.async.wait_group 0;" ::: "memory");
}

// ---------------- float4 math ----------------
__device__ __forceinline__ float4 f4relu(float4 a) {
    return make_float4(fmaxf(a.x, 0.f), fmaxf(a.y, 0.f), fmaxf(a.z, 0.f), fmaxf(a.w, 0.f));
}
__device__ __forceinline__ float4 f4ma(float4 a, float4 b, float4 c) {
    return make_float4(fmaf(a.x, b.x, c.x), fmaf(a.y, b.y, c.y),
                       fmaf(a.z, b.z, c.z), fmaf(a.w, b.w, c.w));
}
__device__ __forceinline__ float4 f4s(float s, float4 a) {
    return make_float4(s * a.x, s * a.y, s * a.z, s * a.w);
}
__device__ __forceinline__ float4 f4sma(float s, float4 a, float4 b) {
    return make_float4(fmaf(s, a.x, b.x), fmaf(s, a.y, b.y),
                       fmaf(s, a.z, b.z), fmaf(s, a.w, b.w));
}
__device__ __forceinline__ float4 f4add(float4 a, float4 b) {
    return make_float4(a.x + b.x, a.y + b.y, a.z + b.z, a.w + b.w);
}

// ---------------- CSR build ----------------
__global__ void k_zero_deg() {
    int i = blockIdx.x * blockDim.x + threadIdx.x;
    if (i < NN) g_deg[i] = 0;
}

__global__ void k_hist(const int* __restrict__ ei) {
    int e = blockIdx.x * blockDim.x + threadIdx.x;
    if (e < EE) atomicAdd(&g_deg[ei[EE + e]], 1);
}

__global__ void k_scan() {
    __shared__ int wsum[32];
    __shared__ int carry;
    int tid = threadIdx.x, lane = tid & 31, w = tid >> 5;
    if (tid == 0) { carry = 0; g_off[0] = 0; }
    __syncthreads();
    for (int base = 0; base < NN; base += 1024) {
        int i = base + tid;
        int v = (i < NN) ? g_deg[i] : 0;
        int x = v;
#pragma unroll
        for (int o = 1; o < 32; o <<= 1) {
            int y = __shfl_up_sync(0xffffffffu, x, o);
            if (lane >= o) x += y;
        }
        if (lane == 31) wsum[w] = x;
        __syncthreads();
        if (w == 0) {
            int s = wsum[lane];
#pragma unroll
            for (int o = 1; o < 32; o <<= 1) {
                int y = __shfl_up_sync(0xffffffffu, s, o);
                if (lane >= o) s += y;
            }
            wsum[lane] = s;
        }
        __syncthreads();
        int incl = x + (w ? wsum[w - 1] : 0) + carry;
        if (i < NN) { g_off[i + 1] = incl; g_cur[i] = incl - v; }
        __syncthreads();
        if (tid == 1023) carry = incl;
        __syncthreads();
    }
}

__global__ void k_scatter(const int* __restrict__ ei, const int* __restrict__ ea) {
    int e = blockIdx.x * blockDim.x + threadIdx.x;
    if (e < EE) {
        int d = ei[EE + e];
        int p = atomicAdd(&g_cur[d], 1);
        g_pack[p] = (ei[e] << 3) | ea[e];
    }
}

// ---------------- merged prologue: W conv + stat zero + node encode ----------
__global__ void k_prep(const float* __restrict__ Wfull, const int* __restrict__ x,
                       const float* __restrict__ ne1, const float* __restrict__ ne2) {
    int i = blockIdx.x * blockDim.x + threadIdx.x;
    if (i < LL * 2 * DD) { g_sumL[i] = 0.f; g_sqL[i] = 0.f; }
    if (i < 2 * LL * DD * DD) {
        float v = Wfull[i];
        __nv_bfloat16 h = __float2bfloat16(v);
        g_Whi[i] = h;
        g_Wlo[i] = __float2bfloat16(v - __bfloat162float(h));
    }
    if (i < NN * 32) {
        int n = i >> 5, c = i & 31;
        int xv = x[n];
        ((float4*)g_h1)[n * 32 + c] = ((const float4*)ne1)[xv * 32 + c];
        ((float4*)g_h2)[n * 32 + c] = ((const float4*)ne2)[xv * 32 + c];
    }
}

// ---------------- gather aggregation (optionally fused prev-layer BN+cross) --
__device__ __forceinline__ void split4(float4 r, uint2* hi, uint2* lo) {
    __nv_bfloat16 hx = __float2bfloat16(r.x), hy = __float2bfloat16(r.y);
    __nv_bfloat16 hz = __float2bfloat16(r.z), hw = __float2bfloat16(r.w);
    __nv_bfloat16 lx = __float2bfloat16(r.x - __bfloat162float(hx));
    __nv_bfloat16 ly = __float2bfloat16(r.y - __bfloat162float(hy));
    __nv_bfloat16 lz = __float2bfloat16(r.z - __bfloat162float(hz));
    __nv_bfloat16 lw = __float2bfloat16(r.w - __bfloat162float(hw));
    hi->x = (uint32_t)__bfloat16_as_ushort(hx) | ((uint32_t)__bfloat16_as_ushort(hy) << 16);
    hi->y = (uint32_t)__bfloat16_as_ushort(hz) | ((uint32_t)__bfloat16_as_ushort(hw) << 16);
    lo->x = (uint32_t)__bfloat16_as_ushort(lx) | ((uint32_t)__bfloat16_as_ushort(ly) << 16);
    lo->y = (uint32_t)__bfloat16_as_ushort(lz) | ((uint32_t)__bfloat16_as_ushort(lw) << 16);
}

template <bool FUSE>
__global__ __launch_bounds__(512) void k_aggregate(const float* __restrict__ eemb,
                                                   const float* __restrict__ eps_ptr,
                                                   const float* __restrict__ gam,
                                                   const float* __restrict__ bet,
                                                   const float* __restrict__ cu,
                                                   int layer) {
    __shared__ float4 s_et[2 * EVV * 32];
    int tid = threadIdx.x;
    const float* et1 = eemb + (0 * LL + layer) * EVV * DD;
    const float* et2 = eemb + (1 * LL + layer) * EVV * DD;
    if (tid < 2 * EVV * 32) {
        if (tid < EVV * 32) s_et[tid] = ((const float4*)et1)[tid];
        else                s_et[tid] = ((const float4*)et2)[tid - EVV * 32];
    }
    __syncthreads();

    int warp = tid >> 5, lane = tid & 31;
    int n = blockIdx.x * 16 + warp;           // grid 1250 * 16 = 20000 exactly

    // BN+cross coefficients of the PREVIOUS layer (feature f = lane*4 .. +3)
    float4 al1, be1, al2, be2;
    float c00 = 0.f, c01 = 0.f, c10 = 0.f, c11 = 0.f;
    if (FUSE) {
        int f = lane * 4, pl = layer - 1;
        const float inv = 1.f / (float)NN;
        const float* ps = g_sumL + pl * 2 * DD;
        const float* pq = g_sqL + pl * 2 * DD;
        float4 s1 = *(const float4*)&ps[f];
        float4 q1 = *(const float4*)&pq[f];
        float4 s2 = *(const float4*)&ps[DD + f];
        float4 q2 = *(const float4*)&pq[DD + f];
        float4 mu1 = f4s(inv, s1), mu2 = f4s(inv, s2);
        float4 rs1 = make_float4(rsqrtf(q1.x * inv - mu1.x * mu1.x + BN_EPS),
                                 rsqrtf(q1.y * inv - mu1.y * mu1.y + BN_EPS),
                                 rsqrtf(q1.z * inv - mu1.z * mu1.z + BN_EPS),
                                 rsqrtf(q1.w * inv - mu1.w * mu1.w + BN_EPS));
        float4 rs2 = make_float4(rsqrtf(q2.x * inv - mu2.x * mu2.x + BN_EPS),
                                 rsqrtf(q2.y * inv - mu2.y * mu2.y + BN_EPS),
                                 rsqrtf(q2.z * inv - mu2.z * mu2.z + BN_EPS),
                                 rsqrtf(q2.w * inv - mu2.w * mu2.w + BN_EPS));
        float4 g1 = *(const float4*)&gam[(0 * LL + pl) * DD + f];
        float4 b1 = *(const float4*)&bet[(0 * LL + pl) * DD + f];
        float4 g2 = *(const float4*)&gam[(1 * LL + pl) * DD + f];
        float4 b2 = *(const float4*)&bet[(1 * LL + pl) * DD + f];
        al1 = make_float4(rs1.x * g1.x, rs1.y * g1.y, rs1.z * g1.z, rs1.w * g1.w);
        al2 = make_float4(rs2.x * g2.x, rs2.y * g2.y, rs2.z * g2.z, rs2.w * g2.w);
        be1 = make_float4(b1.x - mu1.x * al1.x, b1.y - mu1.y * al1.y,
                          b1.z - mu1.z * al1.z, b1.w - mu1.w * al1.w);
        be2 = make_float4(b2.x - mu2.x * al2.x, b2.y - mu2.y * al2.y,
                          b2.z - mu2.z * al2.z, b2.w - mu2.w * al2.w);
        c00 = cu[pl * 4 + 0]; c01 = cu[pl * 4 + 1];
        c10 = cu[pl * 4 + 2]; c11 = cu[pl * 4 + 3];
    }

    const float4* Yv1 = (const float4*)(FUSE ? g_Y1 : g_h1);
    const float4* Yv2 = (const float4*)(FUSE ? g_Y2 : g_h2);

    int beg = g_off[n], deg = g_off[n + 1] - beg;
    float4 acc1 = make_float4(0.f, 0.f, 0.f, 0.f);
    float4 acc2 = make_float4(0.f, 0.f, 0.f, 0.f);

    // transform = prev-layer BN + relu + cross-stitch (identity when !FUSE)
    auto xf = [&](float4 y1, float4 y2, float4& n1, float4& n2) {
        if (FUSE) {
            float4 a1 = f4relu(f4ma(y1, al1, be1));
            float4 a2 = f4relu(f4ma(y2, al2, be2));
            n1 = f4sma(c01, a2, f4s(c00, a1));
            n2 = f4sma(c11, a2, f4s(c10, n1));
        } else { n1 = y1; n2 = y2; }
    };

    for (int base = 0; base < deg; base += 32) {
        int idx = base + lane;
        int pk = (idx < deg) ? __ldg(&g_pack[beg + idx]) : 0;
        int cnt = min(32, deg - base);
        int k = 0;
        for (; k + 4 <= cnt; k += 4) {
            int pa[4];
            float4 u1[4], u2[4];
#pragma unroll
            for (int j = 0; j < 4; j++) pa[j] = __shfl_sync(0xffffffffu, pk, k + j);
#pragma unroll
            for (int j = 0; j < 4; j++) {
                u1[j] = Yv1[(pa[j] >> 3) * 32 + lane];
                u2[j] = Yv2[(pa[j] >> 3) * 32 + lane];
            }
#pragma unroll
            for (int j = 0; j < 4; j++) {
                float4 n1, n2;
                xf(u1[j], u2[j], n1, n2);
                float4 t1 = s_et[(pa[j] & 7) * 32 + lane];
                float4 t2 = s_et[EVV * 32 + (pa[j] & 7) * 32 + lane];
                acc1 = f4add(acc1, f4relu(f4add(n1, t1)));
                acc2 = f4add(acc2, f4relu(f4add(n2, t2)));
            }
        }
        for (; k < cnt; k++) {
            int p = __shfl_sync(0xffffffffu, pk, k);
            float4 n1, n2;
            xf(Yv1[(p >> 3) * 32 + lane], Yv2[(p >> 3) * 32 + lane], n1, n2);
            float4 t1 = s_et[(p & 7) * 32 + lane];
            float4 t2 = s_et[EVV * 32 + (p & 7) * 32 + lane];
            acc1 = f4add(acc1, f4relu(f4add(n1, t1)));
            acc2 = f4add(acc2, f4relu(f4add(n2, t2)));
        }
    }

    float e1 = 1.f + eps_ptr[layer];
    float e2 = 1.f + eps_ptr[LL + layer];
    float4 o1, o2;
    xf(Yv1[n * 32 + lane], Yv2[n * 32 + lane], o1, o2);
    float4 r1 = f4sma(e1, o1, acc1);
    float4 r2 = f4sma(e2, o2, acc2);

    uint2 hi, lo;
    split4(r1, &hi, &lo);
    *(uint2*)&g_A1hi[n * DD + lane * 4] = hi;
    *(uint2*)&g_A1lo[n * DD + lane * 4] = lo;
    split4(r2, &hi, &lo);
    *(uint2*)&g_A2hi[n * DD + lane * 4] = hi;
    *(uint2*)&g_A2lo[n * DD + lane * 4] = lo;
}

// ---------------- HMMA GEMM: Y = A @ W^T + b  (bf16 hi/lo x3, fp32 acc) ------
#define SM_AHI  0
#define SM_ALO  32768
#define SM_WHI  65536
#define SM_WLO  98304
#define SM_GEMM_TOTAL 131072

__global__ __launch_bounds__(256, 1) void k_gemm_tc(const float* __restrict__ bfull,
                                                    int layer) {
    extern __shared__ char smem[];
    uint32_t sbase = smem_u32(smem);
    int tid = threadIdx.x;
    int wid = tid >> 5, lane = tid & 31;

    int t = blockIdx.y;
    const __nv_bfloat16* Ahi = t ? g_A2hi : g_A1hi;
    const __nv_bfloat16* Alo = t ? g_A2lo : g_A1lo;
    const __nv_bfloat16* Whi = g_Whi + (t * LL + layer) * DD * DD;
    const __nv_bfloat16* Wlo = g_Wlo + (t * LL + layer) * DD * DD;
    float* Y = t ? g_Y2 : g_Y1;
    const float* bp = bfull + (t * LL + layer) * DD;
    int m0 = blockIdx.x * 128;

    for (int i = tid; i < 2048; i += 256) {
        int row = i >> 4, ch = i & 15;
        uint32_t so = (uint32_t)row * 256u + (uint32_t)((ch ^ (row & 7)) << 4);
        cp16(sbase + SM_AHI + so, (const char*)(Ahi + (size_t)(m0 + row) * DD) + ch * 16);
        cp16(sbase + SM_ALO + so, (const char*)(Alo + (size_t)(m0 + row) * DD) + ch * 16);
        cp16(sbase + SM_WHI + so, (const char*)(Whi + (size_t)row * DD) + ch * 16);
        cp16(sbase + SM_WLO + so, (const char*)(Wlo + (size_t)row * DD) + ch * 16);
    }
    cp_commit_wait();
    __syncthreads();

    int wm = wid & 3, wn = wid >> 2;
    int grp = lane >> 3, r8 = lane & 7;
    int a_row0 = wm * 32 + (grp & 1) * 8 + r8;
    int b_row0 = wn * 64 + (grp >> 1) * 8 + r8;
    int kselA = grp >> 1;
    int kselB = grp & 1;

    float acc[2][8][4];
#pragma unroll
    for (int i = 0; i < 2; i++)
#pragma unroll
        for (int j = 0; j < 8; j++)
#pragma unroll
            for (int q = 0; q < 4; q++) acc[i][j][q] = 0.f;

#pragma unroll
    for (int p = 0; p < 3; p++) {
        uint32_t Ab = sbase + ((p == 2) ? SM_ALO : SM_AHI);
        uint32_t Bb = sbase + ((p == 1) ? SM_WLO : SM_WHI);
#pragma unroll
        for (int ks = 0; ks < 8; ks++) {
            uint32_t af[2][4], bf[4][4];
            uint32_t aoff = (uint32_t)(((ks * 2 + kselA) ^ r8) << 4);
            ldsm4(af[0], Ab + (uint32_t)a_row0 * 256u + aoff);
            ldsm4(af[1], Ab + (uint32_t)(a_row0 + 16) * 256u + aoff);
            uint32_t boff = (uint32_t)(((ks * 2 + kselB) ^ r8) << 4);
#pragma unroll
            for (int jj = 0; jj < 4; jj++)
                ldsm4(bf[jj], Bb + (uint32_t)(b_row0 + jj * 16) * 256u + boff);
#pragma unroll
            for (int i = 0; i < 2; i++)
#pragma unroll
                for (int j = 0; j < 8; j++)
                    mma16816(acc[i][j], af[i], &bf[j >> 1][(j & 1) * 2]);
        }
    }

    float* gsum = g_sumL + layer * 2 * DD + t * DD;
    float* gsq = g_sqL + layer * 2 * DD + t * DD;
    int qr = lane >> 2, qc = lane & 3;
#pragma unroll
    for (int j = 0; j < 8; j++) {
        int c0 = wn * 64 + j * 8 + qc * 2;
        float bb0 = bp[c0], bb1 = bp[c0 + 1];
        float s0 = 0.f, s1 = 0.f, q0 = 0.f, q1 = 0.f;
#pragma unroll
        for (int i = 0; i < 2; i++) {
#pragma unroll
            for (int h = 0; h < 2; h++) {
                int m = m0 + wm * 32 + i * 16 + qr + h * 8;
                float v0 = acc[i][j][h * 2 + 0] + bb0;
                float v1 = acc[i][j][h * 2 + 1] + bb1;
                if (m < NN) {
                    *(float2*)&Y[m * DD + c0] = make_float2(v0, v1);
                    s0 += v0; s1 += v1;
                    q0 += v0 * v0; q1 += v1 * v1;
                }
            }
        }
#pragma unroll
        for (int off = 4; off < 32; off <<= 1) {
            s0 += __shfl_xor_sync(0xffffffffu, s0, off);
            s1 += __shfl_xor_sync(0xffffffffu, s1, off);
            q0 += __shfl_xor_sync(0xffffffffu, q0, off);
            q1 += __shfl_xor_sync(0xffffffffu, q1, off);
        }
        if (qr == 0) {
            atomicAdd(&gsum[c0], s0);
            atomicAdd(&gsum[c0 + 1], s1);
            atomicAdd(&gsq[c0], q0);
            atomicAdd(&gsq[c0 + 1], q1);
        }
    }
}

// ---------------- final BN + cross-stitch (layer L-1 only, no relu) ----------
__global__ void k_bn_cross_final(const float* __restrict__ gam,
                                 const float* __restrict__ bet,
                                 const float* __restrict__ cu,
                                 float* __restrict__ out) {
    int idx = blockIdx.x * blockDim.x + threadIdx.x;
    if (idx >= NN * 32) return;
    int n = idx >> 5, c4 = idx & 31;
    int f = c4 * 4;
    const int layer = LL - 1;
    const float inv = 1.f / (float)NN;
    const float* gsum = g_sumL + layer * 2 * DD;
    const float* gsq = g_sqL + layer * 2 * DD;

    float4 s1 = *(const float4*)&gsum[f];
    float4 q1 = *(const float4*)&gsq[f];
    float4 s2 = *(const float4*)&gsum[DD + f];
    float4 q2 = *(const float4*)&gsq[DD + f];

    float4 mu1 = f4s(inv, s1), mu2 = f4s(inv, s2);
    float4 rs1 = make_float4(rsqrtf(q1.x * inv - mu1.x * mu1.x + BN_EPS),
                             rsqrtf(q1.y * inv - mu1.y * mu1.y + BN_EPS),
                             rsqrtf(q1.z * inv - mu1.z * mu1.z + BN_EPS),
                             rsqrtf(q1.w * inv - mu1.w * mu1.w + BN_EPS));
    float4 rs2 = make_float4(rsqrtf(q2.x * inv - mu2.x * mu2.x + BN_EPS),
                             rsqrtf(q2.y * inv - mu2.y * mu2.y + BN_EPS),
                             rsqrtf(q2.z * inv - mu2.z * mu2.z + BN_EPS),
                             rsqrtf(q2.w * inv - mu2.w * mu2.w + BN_EPS));

    float4 g1 = *(const float4*)&gam[(0 * LL + layer) * DD + f];
    float4 b1 = *(const float4*)&bet[(0 * LL + layer) * DD + f];
    float4 g2 = *(const float4*)&gam[(1 * LL + layer) * DD + f];
    float4 b2 = *(const float4*)&bet[(1 * LL + layer) * DD + f];

    float4 y1 = ((const float4*)g_Y1)[n * 32 + c4];
    float4 y2 = ((const float4*)g_Y2)[n * 32 + c4];

    y1.x = (y1.x - mu1.x) * rs1.x * g1.x + b1.x;
    y1.y = (y1.y - mu1.y) * rs1.y * g1.y + b1.y;
    y1.z = (y1.z - mu1.z) * rs1.z * g1.z + b1.z;
    y1.w = (y1.w - mu1.w) * rs1.w * g1.w + b1.w;
    y2.x = (y2.x - mu2.x) * rs2.x * g2.x + b2.x;
    y2.y = (y2.y - mu2.y) * rs2.y * g2.y + b2.y;
    y2.z = (y2.z - mu2.z) * rs2.z * g2.z + b2.z;
    y2.w = (y2.w - mu2.w) * rs2.w * g2.w + b2.w;

    float c00 = cu[layer * 4 + 0], c01 = cu[layer * 4 + 1];
    float c10 = cu[layer * 4 + 2], c11 = cu[layer * 4 + 3];

    float4 n1 = make_float4(c00 * y1.x + c01 * y2.x, c00 * y1.y + c01 * y2.y,
                            c00 * y1.z + c01 * y2.z, c00 * y1.w + c01 * y2.w);
    float4 n2 = make_float4(c10 * n1.x + c11 * y2.x, c10 * n1.y + c11 * y2.y,
                            c10 * n1.z + c11 * y2.z, c10 * n1.w + c11 * y2.w);

    ((float4*)out)[n * 32 + c4] = n1;
    ((float4*)out)[NN * 32 + n * 32 + c4] = n2;
}

// ---------------- launch ----------------
extern "C" void kernel_launch(void* const* d_in, const int* in_sizes, int n_in,
                              void* d_out, int out_size) {
    const int* x = (const int*)d_in[0];
    const int* ei = (const int*)d_in[1];
    const int* ea = (const int*)d_in[2];
    const float* ne1 = (const float*)d_in[3];
    const float* ne2 = (const float*)d_in[4];
    const float* eemb = (const float*)d_in[5];
    const float* eps = (const float*)d_in[6];
    const float* W = (const float*)d_in[7];
    const float* b = (const float*)d_in[8];
    const float* gam = (const float*)d_in[9];
    const float* bet = (const float*)d_in[10];
    const float* cu = (const float*)d_in[11];
    float* out = (float*)d_out;

    static int smem_set = 0;
    if (!smem_set) {
        cudaFuncSetAttribute(k_gemm_tc, cudaFuncAttributeMaxDynamicSharedMemorySize,
                             SM_GEMM_TOTAL);
        smem_set = 1;
    }

    k_zero_deg<<<(NN + 255) / 256, 256>>>();
    k_hist<<<(EE + 255) / 256, 256>>>(ei);
    k_scan<<<1, 1024>>>();
    k_scatter<<<(EE + 255) / 256, 256>>>(ei, ea);
    k_prep<<<(NN * 32 + 255) / 256, 256>>>(W, x, ne1, ne2);

    for (int l = 0; l < LL; l++) {
        if (l == 0)
            k_aggregate<false><<<NN / 16, 512>>>(eemb, eps, gam, bet, cu, l);
        else
            k_aggregate<true><<<NN / 16, 512>>>(eemb, eps, gam, bet, cu, l);
        dim3 gg((NN + 127) / 128, 2);
        k_gemm_tc<<<gg, 256, SM_GEMM_TOTAL>>>(b, l);
    }
    k_bn_cross_final<<<(NN * 32 + 255) / 256, 256>>>(gam, bet, cu, out);
}

// round 9
// speedup vs baseline: 1.5599x; 1.2060x over previous
#include <cuda_runtime.h>
#include <cuda_bf16.h>
#include <cuda_fp16.h>
#include <cstdint>

#define NN 20000
#define EE 320000
#define DD 128
#define LL 5
#define EVV 5
#define BN_EPS 1e-5f
#define MPAD 20096   // 157 * 128

// ---------------- device scratch (no allocation allowed) ----------------
__device__ uint2 g_hh[NN * 64];            // fp16 h, [node][tower][128]: uint2 = 4 halves
__device__ float g_Y1[NN * DD];
__device__ float g_Y2[NN * DD];
__device__ __nv_bfloat16 g_A1hi[MPAD * DD];
__device__ __nv_bfloat16 g_A1lo[MPAD * DD];
__device__ __nv_bfloat16 g_A2hi[MPAD * DD];
__device__ __nv_bfloat16 g_A2lo[MPAD * DD];
__device__ __nv_bfloat16 g_Whi[2 * LL * DD * DD];
__device__ __nv_bfloat16 g_Wlo[2 * LL * DD * DD];
__device__ int   g_deg[NN];
__device__ int   g_off[NN + 1];
__device__ int   g_cur[NN];
__device__ int   g_pack[EE];     // (src << 3) | attr
__device__ float g_sumL[LL * 2 * DD];
__device__ float g_sqL[LL * 2 * DD];

// ---------------- PTX helpers ----------------
__device__ __forceinline__ uint32_t smem_u32(const void* p) {
    uint32_t a;
    asm("{ .reg .u64 t; cvta.to.shared.u64 t, %1; cvt.u32.u64 %0, t; }" : "=r"(a) : "l"(p));
    return a;
}
__device__ __forceinline__ void ldsm4(uint32_t* r, uint32_t addr) {
    asm volatile("ldmatrix.sync.aligned.m8n8.x4.shared.b16 {%0,%1,%2,%3}, [%4];"
                 : "=r"(r[0]), "=r"(r[1]), "=r"(r[2]), "=r"(r[3]) : "r"(addr));
}
__device__ __forceinline__ void mma16816(float* d, const uint32_t* a, const uint32_t* b) {
    asm volatile(
        "mma.sync.aligned.m16n8k16.row.col.f32.bf16.bf16.f32 "
        "{%0,%1,%2,%3}, {%4,%5,%6,%7}, {%8,%9}, {%0,%1,%2,%3};"
        : "+f"(d[0]), "+f"(d[1]), "+f"(d[2]), "+f"(d[3])
        : "r"(a[0]), "r"(a[1]), "r"(a[2]), "r"(a[3]), "r"(b[0]), "r"(b[1]));
}
__device__ __forceinline__ void cp16(uint32_t dst, const void* src) {
    asm volatile("cp.async.cg.shared.global [%0], [%1], 16;" :: "r"(dst), "l"(src));
}
__device__ __forceinline__ void cp_commit_wait() {
    asm volatile("cp.async.commit_group;" ::: "memory");
    asm volatile("cp.async.wait_group 0;" ::: "memory");
}

// ---------------- small vector helpers ----------------
__device__ __forceinline__ float4 f4relu(float4 a) {
    return make_float4(fmaxf(a.x, 0.f), fmaxf(a.y, 0.f), fmaxf(a.z, 0.f), fmaxf(a.w, 0.f));
}
__device__ __forceinline__ float4 f4add(float4 a, float4 b) {
    return make_float4(a.x + b.x, a.y + b.y, a.z + b.z, a.w + b.w);
}
__device__ __forceinline__ float4 f4s(float s, float4 a) {
    return make_float4(s * a.x, s * a.y, s * a.z, s * a.w);
}
__device__ __forceinline__ float4 f4sma(float s, float4 a, float4 b) {
    return make_float4(fmaf(s, a.x, b.x), fmaf(s, a.y, b.y),
                       fmaf(s, a.z, b.z), fmaf(s, a.w, b.w));
}
__device__ __forceinline__ float4 h2f4(uint2 u) {
    __half2 a = *(__half2*)&u.x;
    __half2 b = *(__half2*)&u.y;
    float2 fa = __half22float2(a), fb = __half22float2(b);
    return make_float4(fa.x, fa.y, fb.x, fb.y);
}
__device__ __forceinline__ uint2 f4h(float4 v) {
    __half2 a = __floats2half2_rn(v.x, v.y);
    __half2 b = __floats2half2_rn(v.z, v.w);
    uint2 r;
    r.x = *(uint32_t*)&a;
    r.y = *(uint32_t*)&b;
    return r;
}

// ---------------- CSR build ----------------
__global__ void k_zero_deg() {
    int i = blockIdx.x * blockDim.x + threadIdx.x;
    if (i < NN) g_deg[i] = 0;
}

__global__ void k_hist(const int* __restrict__ ei) {
    int e = blockIdx.x * blockDim.x + threadIdx.x;
    if (e < EE) atomicAdd(&g_deg[ei[EE + e]], 1);
}

__global__ void k_scan() {
    __shared__ int wsum[32];
    __shared__ int carry;
    int tid = threadIdx.x, lane = tid & 31, w = tid >> 5;
    if (tid == 0) { carry = 0; g_off[0] = 0; }
    __syncthreads();
    for (int base = 0; base < NN; base += 1024) {
        int i = base + tid;
        int v = (i < NN) ? g_deg[i] : 0;
        int x = v;
#pragma unroll
        for (int o = 1; o < 32; o <<= 1) {
            int y = __shfl_up_sync(0xffffffffu, x, o);
            if (lane >= o) x += y;
        }
        if (lane == 31) wsum[w] = x;
        __syncthreads();
        if (w == 0) {
            int s = wsum[lane];
#pragma unroll
            for (int o = 1; o < 32; o <<= 1) {
                int y = __shfl_up_sync(0xffffffffu, s, o);
                if (lane >= o) s += y;
            }
            wsum[lane] = s;
        }
        __syncthreads();
        int incl = x + (w ? wsum[w - 1] : 0) + carry;
        if (i < NN) { g_off[i + 1] = incl; g_cur[i] = incl - v; }
        __syncthreads();
        if (tid == 1023) carry = incl;
        __syncthreads();
    }
}

__global__ void k_scatter(const int* __restrict__ ei, const int* __restrict__ ea) {
    int e = blockIdx.x * blockDim.x + threadIdx.x;
    if (e < EE) {
        int d = ei[EE + e];
        int p = atomicAdd(&g_cur[d], 1);
        g_pack[p] = (ei[e] << 3) | ea[e];
    }
}

// ---------------- merged prologue: W conv + stat zero + node encode (fp16) ---
__global__ void k_prep(const float* __restrict__ Wfull, const int* __restrict__ x,
                       const float* __restrict__ ne1, const float* __restrict__ ne2) {
    int i = blockIdx.x * blockDim.x + threadIdx.x;
    if (i < LL * 2 * DD) { g_sumL[i] = 0.f; g_sqL[i] = 0.f; }
    if (i < 2 * LL * DD * DD) {
        float v = Wfull[i];
        __nv_bfloat16 h = __float2bfloat16(v);
        g_Whi[i] = h;
        g_Wlo[i] = __float2bfloat16(v - __bfloat162float(h));
    }
    if (i < NN * 32) {
        int n = i >> 5, c = i & 31;
        int xv = x[n];
        g_hh[n * 64 + c] = f4h(((const float4*)ne1)[xv * 32 + c]);
        g_hh[n * 64 + 32 + c] = f4h(((const float4*)ne2)[xv * 32 + c]);
    }
}

// ---------------- gather aggregation: fp16 h rows, writes bf16 hi/lo A -------
__device__ __forceinline__ void split4(float4 r, uint2* hi, uint2* lo) {
    __nv_bfloat16 hx = __float2bfloat16(r.x), hy = __float2bfloat16(r.y);
    __nv_bfloat16 hz = __float2bfloat16(r.z), hw = __float2bfloat16(r.w);
    __nv_bfloat16 lx = __float2bfloat16(r.x - __bfloat162float(hx));
    __nv_bfloat16 ly = __float2bfloat16(r.y - __bfloat162float(hy));
    __nv_bfloat16 lz = __float2bfloat16(r.z - __bfloat162float(hz));
    __nv_bfloat16 lw = __float2bfloat16(r.w - __bfloat162float(hw));
    hi->x = (uint32_t)__bfloat16_as_ushort(hx) | ((uint32_t)__bfloat16_as_ushort(hy) << 16);
    hi->y = (uint32_t)__bfloat16_as_ushort(hz) | ((uint32_t)__bfloat16_as_ushort(hw) << 16);
    lo->x = (uint32_t)__bfloat16_as_ushort(lx) | ((uint32_t)__bfloat16_as_ushort(ly) << 16);
    lo->y = (uint32_t)__bfloat16_as_ushort(lz) | ((uint32_t)__bfloat16_as_ushort(lw) << 16);
}

__global__ __launch_bounds__(512) void k_aggregate(const float* __restrict__ eemb,
                                                   const float* __restrict__ eps_ptr,
                                                   int layer) {
    __shared__ float4 s_et[2 * EVV * 32];
    int tid = threadIdx.x;
    const float* et1 = eemb + (0 * LL + layer) * EVV * DD;
    const float* et2 = eemb + (1 * LL + layer) * EVV * DD;
    if (tid < 2 * EVV * 32) {
        if (tid < EVV * 32) s_et[tid] = ((const float4*)et1)[tid];
        else                s_et[tid] = ((const float4*)et2)[tid - EVV * 32];
    }
    __syncthreads();

    int warp = tid >> 5, lane = tid & 31;
    int n = blockIdx.x * 16 + warp;           // grid 1250 * 16 = 20000 exactly

    int beg = g_off[n], deg = g_off[n + 1] - beg;
    float4 acc1 = make_float4(0.f, 0.f, 0.f, 0.f);
    float4 acc2 = make_float4(0.f, 0.f, 0.f, 0.f);

    for (int base = 0; base < deg; base += 32) {
        int idx = base + lane;
        int pk = (idx < deg) ? __ldg(&g_pack[beg + idx]) : 0;
        int cnt = min(32, deg - base);
        int k = 0;
        for (; k + 4 <= cnt; k += 4) {
            int pa[4];
            uint2 u1[4], u2[4];
#pragma unroll
            for (int j = 0; j < 4; j++) pa[j] = __shfl_sync(0xffffffffu, pk, k + j);
#pragma unroll
            for (int j = 0; j < 4; j++) {
                int s = pa[j] >> 3;
                u1[j] = g_hh[s * 64 + lane];
                u2[j] = g_hh[s * 64 + 32 + lane];
            }
#pragma unroll
            for (int j = 0; j < 4; j++) {
                int a = pa[j] & 7;
                acc1 = f4add(acc1, f4relu(f4add(h2f4(u1[j]), s_et[a * 32 + lane])));
                acc2 = f4add(acc2, f4relu(f4add(h2f4(u2[j]), s_et[EVV * 32 + a * 32 + lane])));
            }
        }
        for (; k < cnt; k++) {
            int p = __shfl_sync(0xffffffffu, pk, k);
            int s = p >> 3, a = p & 7;
            acc1 = f4add(acc1, f4relu(f4add(h2f4(g_hh[s * 64 + lane]), s_et[a * 32 + lane])));
            acc2 = f4add(acc2, f4relu(f4add(h2f4(g_hh[s * 64 + 32 + lane]),
                                            s_et[EVV * 32 + a * 32 + lane])));
        }
    }
    float e1 = 1.f + eps_ptr[layer];
    float e2 = 1.f + eps_ptr[LL + layer];
    float4 o1 = h2f4(g_hh[n * 64 + lane]);
    float4 o2 = h2f4(g_hh[n * 64 + 32 + lane]);
    float4 r1 = f4sma(e1, o1, acc1);
    float4 r2 = f4sma(e2, o2, acc2);

    uint2 hi, lo;
    split4(r1, &hi, &lo);
    *(uint2*)&g_A1hi[n * DD + lane * 4] = hi;
    *(uint2*)&g_A1lo[n * DD + lane * 4] = lo;
    split4(r2, &hi, &lo);
    *(uint2*)&g_A2hi[n * DD + lane * 4] = hi;
    *(uint2*)&g_A2lo[n * DD + lane * 4] = lo;
}

// ---------------- HMMA GEMM: Y = A @ W^T + b  (bf16 hi/lo x3, fp32 acc) ------
#define SM_AHI  0
#define SM_ALO  32768
#define SM_WHI  65536
#define SM_WLO  98304
#define SM_GEMM_TOTAL 131072

__global__ __launch_bounds__(256, 1) void k_gemm_tc(const float* __restrict__ bfull,
                                                    int layer) {
    extern __shared__ char smem[];
    uint32_t sbase = smem_u32(smem);
    int tid = threadIdx.x;
    int wid = tid >> 5, lane = tid & 31;

    int t = blockIdx.y;
    const __nv_bfloat16* Ahi = t ? g_A2hi : g_A1hi;
    const __nv_bfloat16* Alo = t ? g_A2lo : g_A1lo;
    const __nv_bfloat16* Whi = g_Whi + (t * LL + layer) * DD * DD;
    const __nv_bfloat16* Wlo = g_Wlo + (t * LL + layer) * DD * DD;
    float* Y = t ? g_Y2 : g_Y1;
    const float* bp = bfull + (t * LL + layer) * DD;
    int m0 = blockIdx.x * 128;

    for (int i = tid; i < 2048; i += 256) {
        int row = i >> 4, ch = i & 15;
        uint32_t so = (uint32_t)row * 256u + (uint32_t)((ch ^ (row & 7)) << 4);
        cp16(sbase + SM_AHI + so, (const char*)(Ahi + (size_t)(m0 + row) * DD) + ch * 16);
        cp16(sbase + SM_ALO + so, (const char*)(Alo + (size_t)(m0 + row) * DD) + ch * 16);
        cp16(sbase + SM_WHI + so, (const char*)(Whi + (size_t)row * DD) + ch * 16);
        cp16(sbase + SM_WLO + so, (const char*)(Wlo + (size_t)row * DD) + ch * 16);
    }
    cp_commit_wait();
    __syncthreads();

    int wm = wid & 3, wn = wid >> 2;
    int grp = lane >> 3, r8 = lane & 7;
    int a_row0 = wm * 32 + (grp & 1) * 8 + r8;
    int b_row0 = wn * 64 + (grp >> 1) * 8 + r8;
    int kselA = grp >> 1;
    int kselB = grp & 1;

    float acc[2][8][4];
#pragma unroll
    for (int i = 0; i < 2; i++)
#pragma unroll
        for (int j = 0; j < 8; j++)
#pragma unroll
            for (int q = 0; q < 4; q++) acc[i][j][q] = 0.f;

#pragma unroll
    for (int p = 0; p < 3; p++) {
        uint32_t Ab = sbase + ((p == 2) ? SM_ALO : SM_AHI);
        uint32_t Bb = sbase + ((p == 1) ? SM_WLO : SM_WHI);
#pragma unroll
        for (int ks = 0; ks < 8; ks++) {
            uint32_t af[2][4], bf[4][4];
            uint32_t aoff = (uint32_t)(((ks * 2 + kselA) ^ r8) << 4);
            ldsm4(af[0], Ab + (uint32_t)a_row0 * 256u + aoff);
            ldsm4(af[1], Ab + (uint32_t)(a_row0 + 16) * 256u + aoff);
            uint32_t boff = (uint32_t)(((ks * 2 + kselB) ^ r8) << 4);
#pragma unroll
            for (int jj = 0; jj < 4; jj++)
                ldsm4(bf[jj], Bb + (uint32_t)(b_row0 + jj * 16) * 256u + boff);
#pragma unroll
            for (int i = 0; i < 2; i++)
#pragma unroll
                for (int j = 0; j < 8; j++)
                    mma16816(acc[i][j], af[i], &bf[j >> 1][(j & 1) * 2]);
        }
    }

    float* gsum = g_sumL + layer * 2 * DD + t * DD;
    float* gsq = g_sqL + layer * 2 * DD + t * DD;
    int qr = lane >> 2, qc = lane & 3;
#pragma unroll
    for (int j = 0; j < 8; j++) {
        int c0 = wn * 64 + j * 8 + qc * 2;
        float bb0 = bp[c0], bb1 = bp[c0 + 1];
        float s0 = 0.f, s1 = 0.f, q0 = 0.f, q1 = 0.f;
#pragma unroll
        for (int i = 0; i < 2; i++) {
#pragma unroll
            for (int h = 0; h < 2; h++) {
                int m = m0 + wm * 32 + i * 16 + qr + h * 8;
                float v0 = acc[i][j][h * 2 + 0] + bb0;
                float v1 = acc[i][j][h * 2 + 1] + bb1;
                if (m < NN) {
                    *(float2*)&Y[m * DD + c0] = make_float2(v0, v1);
                    s0 += v0; s1 += v1;
                    q0 += v0 * v0; q1 += v1 * v1;
                }
            }
        }
#pragma unroll
        for (int off = 4; off < 32; off <<= 1) {
            s0 += __shfl_xor_sync(0xffffffffu, s0, off);
            s1 += __shfl_xor_sync(0xffffffffu, s1, off);
            q0 += __shfl_xor_sync(0xffffffffu, q0, off);
            q1 += __shfl_xor_sync(0xffffffffu, q1, off);
        }
        if (qr == 0) {
            atomicAdd(&gsum[c0], s0);
            atomicAdd(&gsum[c0 + 1], s1);
            atomicAdd(&gsq[c0], q0);
            atomicAdd(&gsq[c0 + 1], q1);
        }
    }
}

// ---------------- BN + relu + cross-stitch (per node) ----------------
__global__ void k_bn_cross(const float* __restrict__ gam,
                           const float* __restrict__ bet,
                           const float* __restrict__ cu,
                           int layer, int last, float* __restrict__ out) {
    int idx = blockIdx.x * blockDim.x + threadIdx.x;
    if (idx >= NN * 32) return;
    int n = idx >> 5, c4 = idx & 31;
    int f = c4 * 4;
    const float inv = 1.f / (float)NN;
    const float* gsum = g_sumL + layer * 2 * DD;
    const float* gsq = g_sqL + layer * 2 * DD;

    float4 s1 = *(const float4*)&gsum[f];
    float4 q1 = *(const float4*)&gsq[f];
    float4 s2 = *(const float4*)&gsum[DD + f];
    float4 q2 = *(const float4*)&gsq[DD + f];

    float4 mu1 = f4s(inv, s1), mu2 = f4s(inv, s2);
    float4 rs1 = make_float4(rsqrtf(q1.x * inv - mu1.x * mu1.x + BN_EPS),
                             rsqrtf(q1.y * inv - mu1.y * mu1.y + BN_EPS),
                             rsqrtf(q1.z * inv - mu1.z * mu1.z + BN_EPS),
                             rsqrtf(q1.w * inv - mu1.w * mu1.w + BN_EPS));
    float4 rs2 = make_float4(rsqrtf(q2.x * inv - mu2.x * mu2.x + BN_EPS),
                             rsqrtf(q2.y * inv - mu2.y * mu2.y + BN_EPS),
                             rsqrtf(q2.z * inv - mu2.z * mu2.z + BN_EPS),
                             rsqrtf(q2.w * inv - mu2.w * mu2.w + BN_EPS));

    float4 g1 = *(const float4*)&gam[(0 * LL + layer) * DD + f];
    float4 b1 = *(const float4*)&bet[(0 * LL + layer) * DD + f];
    float4 g2 = *(const float4*)&gam[(1 * LL + layer) * DD + f];
    float4 b2 = *(const float4*)&bet[(1 * LL + layer) * DD + f];

    float4 y1 = ((const float4*)g_Y1)[n * 32 + c4];
    float4 y2 = ((const float4*)g_Y2)[n * 32 + c4];

    y1.x = (y1.x - mu1.x) * rs1.x * g1.x + b1.x;
    y1.y = (y1.y - mu1.y) * rs1.y * g1.y + b1.y;
    y1.z = (y1.z - mu1.z) * rs1.z * g1.z + b1.z;
    y1.w = (y1.w - mu1.w) * rs1.w * g1.w + b1.w;
    y2.x = (y2.x - mu2.x) * rs2.x * g2.x + b2.x;
    y2.y = (y2.y - mu2.y) * rs2.y * g2.y + b2.y;
    y2.z = (y2.z - mu2.z) * rs2.z * g2.z + b2.z;
    y2.w = (y2.w - mu2.w) * rs2.w * g2.w + b2.w;

    if (!last) {
        y1 = f4relu(y1);
        y2 = f4relu(y2);
    }

    float c00 = cu[layer * 4 + 0], c01 = cu[layer * 4 + 1];
    float c10 = cu[layer * 4 + 2], c11 = cu[layer * 4 + 3];

    float4 n1 = make_float4(c00 * y1.x + c01 * y2.x, c00 * y1.y + c01 * y2.y,
                            c00 * y1.z + c01 * y2.z, c00 * y1.w + c01 * y2.w);
    float4 n2 = make_float4(c10 * n1.x + c11 * y2.x, c10 * n1.y + c11 * y2.y,
                            c10 * n1.z + c11 * y2.z, c10 * n1.w + c11 * y2.w);

    if (last) {
        ((float4*)out)[n * 32 + c4] = n1;
        ((float4*)out)[NN * 32 + n * 32 + c4] = n2;
    } else {
        g_hh[n * 64 + c4] = f4h(n1);
        g_hh[n * 64 + 32 + c4] = f4h(n2);
    }
}

// ---------------- launch ----------------
extern "C" void kernel_launch(void* const* d_in, const int* in_sizes, int n_in,
                              void* d_out, int out_size) {
    const int* x = (const int*)d_in[0];
    const int* ei = (const int*)d_in[1];
    const int* ea = (const int*)d_in[2];
    const float* ne1 = (const float*)d_in[3];
    const float* ne2 = (const float*)d_in[4];
    const float* eemb = (const float*)d_in[5];
    const float* eps = (const float*)d_in[6];
    const float* W = (const float*)d_in[7];
    const float* b = (const float*)d_in[8];
    const float* gam = (const float*)d_in[9];
    const float* bet = (const float*)d_in[10];
    const float* cu = (const float*)d_in[11];
    float* out = (float*)d_out;

    static int smem_set = 0;
    if (!smem_set) {
        cudaFuncSetAttribute(k_gemm_tc, cudaFuncAttributeMaxDynamicSharedMemorySize,
                             SM_GEMM_TOTAL);
        smem_set = 1;
    }

    k_zero_deg<<<(NN + 255) / 256, 256>>>();
    k_hist<<<(EE + 255) / 256, 256>>>(ei);
    k_scan<<<1, 1024>>>();
    k_scatter<<<(EE + 255) / 256, 256>>>(ei, ea);
    k_prep<<<(NN * 32 + 255) / 256, 256>>>(W, x, ne1, ne2);

    for (int l = 0; l < LL; l++) {
        k_aggregate<<<NN / 16, 512>>>(eemb, eps, l);
        dim3 gg((NN + 127) / 128, 2);
        k_gemm_tc<<<gg, 256, SM_GEMM_TOTAL>>>(b, l);
        k_bn_cross<<<(NN * 32 + 255) / 256, 256>>>(gam, bet, cu, l, (l == LL - 1) ? 1 : 0, out);
    }
}